// round 11
// baseline (speedup 1.0000x reference)
#include <cuda_runtime.h>

#define N_PTS 16384
#define HID   256
#define RT    8             // rows per MLP block
#define PTILE 1024          // column tile for pos path
#define SB    256           // symmetry tile size
#define NB    (N_PTS/SB)    // 64
#define POS_BLOCKS 4096     // 2048 row-groups x 2 column halves
#define NEG_TILES  (NB*(NB+1)/2)   // 2080

__device__ float g_gen[N_PTS * 2];
__device__ float g_spos[2][N_PTS];
__device__ float g_pneg[NB][N_PTS];   // partial neg sums: [originColBlock][row]

__device__ __forceinline__ float fsqrt_fast(float x){ float r; asm("sqrt.approx.f32 %0, %1;" : "=f"(r) : "f"(x)); return r; }
__device__ __forceinline__ float fexp2_fast(float x){ float r; asm("ex2.approx.f32 %0, %1;"  : "=f"(r) : "f"(x)); return r; }
__device__ __forceinline__ float flog2_fast(float x){ float r; asm("lg2.approx.f32 %0, %1;"  : "=f"(r) : "f"(x)); return r; }

#define KCONST 28.853900817779268f    // 1/(TEMP*ln2)
#define TLN2C  0.034657359027997264f  // TEMP*ln2
#define BIASC  64.0f

__device__ __forceinline__ float selu_f(float x){
    const float L  = 1.0507009873554805f;
    const float LA = 1.7580993408473766f;   // L * alpha
    float e   = fexp2_fast(x * 1.4426950408889634f);
    float neg = LA * (e - 1.0f);
    return x > 0.0f ? L * x : neg;
}

// ---------------- MLP ----------------
// 128 threads/block; thread t owns output neurons t and t+128 for RT=8 rows.
// Small row tile keeps regs/smem low -> ~10 blocks/SM for latency hiding.
template<int IN>
__device__ __forceinline__ void mlp_layer(const float (*in_sh)[260], float (*out_sh)[260],
                                          const float* __restrict__ W,
                                          const float* __restrict__ B, int t)
{
    float acca[RT], accb[RT];
    float bva = B[t], bvb = B[t + 128];
    #pragma unroll
    for (int r = 0; r < RT; r++){ acca[r] = bva; accb[r] = bvb; }

    #pragma unroll 1
    for (int k = 0; k < IN; k += 8){
        const float* Wk = W + k * HID + t;
        float wa[8], wb[8];
        #pragma unroll
        for (int i = 0; i < 8; i++){ wa[i] = Wk[i * HID]; wb[i] = Wk[i * HID + 128]; }
        #pragma unroll
        for (int r = 0; r < RT; r++){
            float4 h0 = *reinterpret_cast<const float4*>(&in_sh[r][k]);
            float4 h1 = *reinterpret_cast<const float4*>(&in_sh[r][k+4]);
            float a = acca[r], b = accb[r];
            a = fmaf(h0.x, wa[0], a); b = fmaf(h0.x, wb[0], b);
            a = fmaf(h0.y, wa[1], a); b = fmaf(h0.y, wb[1], b);
            a = fmaf(h0.z, wa[2], a); b = fmaf(h0.z, wb[2], b);
            a = fmaf(h0.w, wa[3], a); b = fmaf(h0.w, wb[3], b);
            a = fmaf(h1.x, wa[4], a); b = fmaf(h1.x, wb[4], b);
            a = fmaf(h1.y, wa[5], a); b = fmaf(h1.y, wb[5], b);
            a = fmaf(h1.z, wa[6], a); b = fmaf(h1.z, wb[6], b);
            a = fmaf(h1.w, wa[7], a); b = fmaf(h1.w, wb[7], b);
            acca[r] = a; accb[r] = b;
        }
    }
    #pragma unroll
    for (int r = 0; r < RT; r++){
        out_sh[r][t]       = selu_f(acca[r]);
        out_sh[r][t + 128] = selu_f(accb[r]);
    }
}

__global__ __launch_bounds__(128) void mlp_kernel(
    const float* __restrict__ z,
    const float* __restrict__ W1, const float* __restrict__ b1,
    const float* __restrict__ W2, const float* __restrict__ b2,
    const float* __restrict__ W3, const float* __restrict__ b3,
    const float* __restrict__ W4, const float* __restrict__ b4,
    const float* __restrict__ W5, const float* __restrict__ b5)
{
    __shared__ float ha[RT][260];
    __shared__ float hb[RT][260];
    int t    = threadIdx.x;
    int row0 = blockIdx.x * RT;

    for (int e = t; e < RT * 32; e += 128) ha[e >> 5][e & 31] = z[row0 * 32 + e];
    __syncthreads();

    mlp_layer<32 >(ha, hb, W1, b1, t);  __syncthreads();
    mlp_layer<256>(hb, ha, W2, b2, t);  __syncthreads();
    mlp_layer<256>(ha, hb, W3, b3, t);  __syncthreads();
    mlp_layer<256>(hb, ha, W4, b4, t);  __syncthreads();
    // layer-4 output lives in ha

    // final 256 -> 2 projection: 16 threads, one (row, dim) each
    if (t < RT * 2){
        int r = t >> 1, d = t & 1;
        float s = b5[d];
        #pragma unroll 4
        for (int k = 0; k < HID; k++) s = fmaf(ha[r][k], W5[k*2 + d], s);
        g_gen[(row0 + r) * 2 + d] = s;
    }
}

// ---------------- Fused energy kernel ----------------
// Blocks [0, POS_BLOCKS): pos path. Block p: rows (p>>1)*8..+7, cols half (p&1).
// Blocks [POS_BLOCKS, +NEG_TILES): neg path, triangular tile (a<=b) of 256x256
// over the symmetric gen-gen matrix; off-diag tiles credit both row and column
// sums. All block types have equal per-warp MUFU work (256 iters) for packing.
// Fixed bias 64 inside exp2 cancels exactly in the final pos/neg log ratio.
__global__ __launch_bounds__(256) void energy_kernel(const float* __restrict__ pos)
{
    __shared__ __align__(16) float smem_raw[2560];   // 10KB, aliased per path

    int tid  = threadIdx.x;
    int lane = tid & 31;
    int w    = tid >> 5;

    if (blockIdx.x < POS_BLOCKS){
        float2* sp = reinterpret_cast<float2*>(smem_raw);   // 1024 float2 = 8KB
        int rg   = blockIdx.x >> 1;
        int half = blockIdx.x & 1;
        int row  = rg * 8 + w;

        float gx = g_gen[row*2], gy = g_gen[row*2 + 1];
        const float2* posv = reinterpret_cast<const float2*>(pos);

        float sps = 0.0f;
        int base = half * (N_PTS / 2);
        for (int tb = base; tb < base + N_PTS/2; tb += PTILE){
            __syncthreads();
            for (int e = tid; e < PTILE; e += 256) sp[e] = posv[tb + e];
            __syncthreads();
            #pragma unroll 8
            for (int j = lane; j < PTILE; j += 32){
                float2 p = sp[j];
                float dx = gx - p.x, dy = gy - p.y;
                float d  = fsqrt_fast(fmaf(dy, dy, dx*dx));
                sps += fexp2_fast(fmaf(d, -KCONST, BIASC));
            }
        }
        #pragma unroll
        for (int o = 16; o; o >>= 1) sps += __shfl_xor_sync(0xffffffffu, sps, o);
        if (lane == 0) g_spos[half][row] = sps;
    } else {
        int t = blockIdx.x - POS_BLOCKS;
        // triangular decode: offset(a) = a*NB - a*(a-1)/2, b = a + t - offset(a)
        int a = (int)(((float)NB + 0.5f) - fsqrt_fast(((float)NB + 0.5f)*((float)NB + 0.5f) - 2.0f*(float)t));
        if (a > NB - 1) a = NB - 1;
        while (a > 0 && a*NB - (a*(a-1))/2 > t) a--;
        while ((a+1)*NB - ((a+1)*a)/2 <= t) a++;
        int b = a + (t - (a*NB - (a*(a-1))/2));

        float2* shr = reinterpret_cast<float2*>(smem_raw);                 // 256 float2 = 2KB
        float (*csum_sh)[SB] = reinterpret_cast<float (*)[SB]>(smem_raw + 512); // 8x256 = 8KB

        const float2* genv = reinterpret_cast<const float2*>(g_gen);

        // stage rows (block a)
        for (int e = tid; e < SB; e += 256) shr[e] = genv[a*SB + e];
        __syncthreads();

        // columns (block b) in registers: lane holds 8 points
        float cx[8], cy[8], csum[8];
        #pragma unroll
        for (int cs = 0; cs < 8; cs++){
            float2 c = genv[b*SB + cs*32 + lane];
            cx[cs] = c.x; cy[cs] = c.y; csum[cs] = 0.0f;
        }

        bool diag = (a == b);

        #pragma unroll 1
        for (int r = 0; r < 32; r++){
            int rloc = w * 32 + r;
            float2 rp = shr[rloc];
            int rl = diag ? rloc : -1;
            float rs = 0.0f;
            #pragma unroll
            for (int cs = 0; cs < 8; cs++){
                float dx = rp.x - cx[cs];
                float dy = rp.y - cy[cs];
                float d  = fsqrt_fast(fmaf(dy, dy, dx*dx));
                float e  = fexp2_fast(fmaf(d, -KCONST, BIASC));
                if (cs*32 + lane == rl) e = 0.0f;
                rs += e;
                csum[cs] += e;
            }
            #pragma unroll
            for (int o = 16; o; o >>= 1) rs += __shfl_xor_sync(0xffffffffu, rs, o);
            if (lane == 0) g_pneg[b][a*SB + rloc] = rs;
        }

        if (!diag){
            #pragma unroll
            for (int cs = 0; cs < 8; cs++) csum_sh[w][cs*32 + lane] = csum[cs];
            __syncthreads();
            for (int c = tid; c < SB; c += 256){
                float s = 0.0f;
                #pragma unroll
                for (int ww = 0; ww < 8; ww++) s += csum_sh[ww][c];
                g_pneg[a][b*SB + c] = s;
            }
        }
    }
}

// ---------------- Final reduce ----------------
__global__ __launch_bounds__(256) void reduce_kernel(float* __restrict__ out)
{
    int i = blockIdx.x * 256 + threadIdx.x;
    float sp = g_spos[0][i] + g_spos[1][i];
    float sn = 0.0f;
    #pragma unroll
    for (int k = 0; k < NB; k++) sn += g_pneg[k][i];
    out[i] = TLN2C * (flog2_fast(sn) - flog2_fast(sp));
}

extern "C" void kernel_launch(void* const* d_in, const int* in_sizes, int n_in,
                              void* d_out, int out_size)
{
    const float* pos = (const float*)d_in[0];
    const float* z   = (const float*)d_in[1];
    const float* W1  = (const float*)d_in[2];  const float* b1 = (const float*)d_in[3];
    const float* W2  = (const float*)d_in[4];  const float* b2 = (const float*)d_in[5];
    const float* W3  = (const float*)d_in[6];  const float* b3 = (const float*)d_in[7];
    const float* W4  = (const float*)d_in[8];  const float* b4 = (const float*)d_in[9];
    const float* W5  = (const float*)d_in[10]; const float* b5 = (const float*)d_in[11];
    (void)in_sizes; (void)n_in; (void)out_size;

    mlp_kernel<<<N_PTS / RT, 128>>>(z, W1, b1, W2, b2, W3, b3, W4, b4, W5, b5);
    energy_kernel<<<POS_BLOCKS + NEG_TILES, 256>>>(pos);
    reduce_kernel<<<N_PTS / 256, 256>>>((float*)d_out);
}

// round 12
// speedup vs baseline: 1.1038x; 1.1038x over previous
#include <cuda_runtime.h>

#define N_PTS 16384
#define HID   256
#define RT    16            // rows per MLP block
#define PTILE 1024          // column tile for pos path
#define SB    256           // symmetry tile size
#define NB    (N_PTS/SB)    // 64
#define POS_BLOCKS 4096     // 2048 row-groups x 2 column halves
#define NEG_TILES  (NB*(NB+1)/2)   // 2080

__device__ float g_gen[N_PTS * 2];
__device__ float g_spos[2][N_PTS];
__device__ float g_pneg[NB][N_PTS];   // partial neg sums: [originColBlock][row]

__device__ __forceinline__ float fsqrt_fast(float x){ float r; asm("sqrt.approx.f32 %0, %1;" : "=f"(r) : "f"(x)); return r; }
__device__ __forceinline__ float fexp2_fast(float x){ float r; asm("ex2.approx.f32 %0, %1;"  : "=f"(r) : "f"(x)); return r; }
__device__ __forceinline__ float flog2_fast(float x){ float r; asm("lg2.approx.f32 %0, %1;"  : "=f"(r) : "f"(x)); return r; }

#define KCONST 28.853900817779268f    // 1/(TEMP*ln2)
#define TLN2C  0.034657359027997264f  // TEMP*ln2
#define BIASC  64.0f

__device__ __forceinline__ float selu_f(float x){
    const float L  = 1.0507009873554805f;
    const float LA = 1.7580993408473766f;   // L * alpha
    float e   = fexp2_fast(x * 1.4426950408889634f);
    float neg = LA * (e - 1.0f);
    return x > 0.0f ? L * x : neg;
}

// ---------------- MLP ----------------
// 128 threads/block; thread t owns neurons 2t and 2t+1 (float2 weight loads),
// RT=16 rows. Weight loads are software-pipelined one chunk ahead so the
// FFMA block never waits on a fresh LDG.
__device__ __forceinline__ void chunk_fma(const float (*in_sh)[260], int k,
                                          const float2* w, float* acca, float* accb)
{
    #pragma unroll
    for (int r = 0; r < RT; r++){
        float4 h0 = *reinterpret_cast<const float4*>(&in_sh[r][k]);
        float4 h1 = *reinterpret_cast<const float4*>(&in_sh[r][k+4]);
        float a = acca[r], b = accb[r];
        a = fmaf(h0.x, w[0].x, a); b = fmaf(h0.x, w[0].y, b);
        a = fmaf(h0.y, w[1].x, a); b = fmaf(h0.y, w[1].y, b);
        a = fmaf(h0.z, w[2].x, a); b = fmaf(h0.z, w[2].y, b);
        a = fmaf(h0.w, w[3].x, a); b = fmaf(h0.w, w[3].y, b);
        a = fmaf(h1.x, w[4].x, a); b = fmaf(h1.x, w[4].y, b);
        a = fmaf(h1.y, w[5].x, a); b = fmaf(h1.y, w[5].y, b);
        a = fmaf(h1.z, w[6].x, a); b = fmaf(h1.z, w[6].y, b);
        a = fmaf(h1.w, w[7].x, a); b = fmaf(h1.w, w[7].y, b);
        acca[r] = a; accb[r] = b;
    }
}

template<int IN>
__device__ __forceinline__ void mlp_layer(const float (*in_sh)[260], float (*out_sh)[260],
                                          const float* __restrict__ W,
                                          const float* __restrict__ B, int t)
{
    float acca[RT], accb[RT];
    float2 bv = *reinterpret_cast<const float2*>(&B[2*t]);
    #pragma unroll
    for (int r = 0; r < RT; r++){ acca[r] = bv.x; accb[r] = bv.y; }

    const float2* Wv = reinterpret_cast<const float2*>(W);   // Wv[k*128 + t] = {W[k][2t], W[k][2t+1]}

    float2 wc[8], wn[8];
    #pragma unroll
    for (int i = 0; i < 8; i++) wc[i] = Wv[i * 128 + t];

    #pragma unroll 1
    for (int k = 0; k < IN - 8; k += 8){
        #pragma unroll
        for (int i = 0; i < 8; i++) wn[i] = Wv[(k + 8 + i) * 128 + t];
        chunk_fma(in_sh, k, wc, acca, accb);
        #pragma unroll
        for (int i = 0; i < 8; i++) wc[i] = wn[i];
    }
    chunk_fma(in_sh, IN - 8, wc, acca, accb);

    #pragma unroll
    for (int r = 0; r < RT; r++){
        out_sh[r][2*t]     = selu_f(acca[r]);
        out_sh[r][2*t + 1] = selu_f(accb[r]);
    }
}

__global__ __launch_bounds__(128) void mlp_kernel(
    const float* __restrict__ z,
    const float* __restrict__ W1, const float* __restrict__ b1,
    const float* __restrict__ W2, const float* __restrict__ b2,
    const float* __restrict__ W3, const float* __restrict__ b3,
    const float* __restrict__ W4, const float* __restrict__ b4,
    const float* __restrict__ W5, const float* __restrict__ b5)
{
    __shared__ float ha[RT][260];
    __shared__ float hb[RT][260];
    int t    = threadIdx.x;
    int row0 = blockIdx.x * RT;

    for (int e = t; e < RT * 32; e += 128) ha[e >> 5][e & 31] = z[row0 * 32 + e];
    __syncthreads();

    mlp_layer<32 >(ha, hb, W1, b1, t);  __syncthreads();
    mlp_layer<256>(hb, ha, W2, b2, t);  __syncthreads();
    mlp_layer<256>(ha, hb, W3, b3, t);  __syncthreads();
    mlp_layer<256>(hb, ha, W4, b4, t);  __syncthreads();
    // layer-4 output lives in ha

    // final 256 -> 2 projection: 32 threads, one (row, dim) each
    if (t < RT * 2){
        int r = t >> 1, d = t & 1;
        float s = b5[d];
        #pragma unroll 4
        for (int k = 0; k < HID; k++) s = fmaf(ha[r][k], W5[k*2 + d], s);
        g_gen[(row0 + r) * 2 + d] = s;
    }
}

// ---------------- Fused energy kernel ----------------
// Blocks [0, POS_BLOCKS): pos path. Block p: rows (p>>1)*8..+7, cols half (p&1).
// Blocks [POS_BLOCKS, +NEG_TILES): neg path, triangular tile (a<=b) of 256x256
// over the symmetric gen-gen matrix; off-diag tiles credit both row and column
// sums. All block types have equal per-warp MUFU work (256 iters) for packing.
// Fixed bias 64 inside exp2 cancels exactly in the final pos/neg log ratio.
__global__ __launch_bounds__(256) void energy_kernel(const float* __restrict__ pos)
{
    __shared__ __align__(16) float smem_raw[2560];   // 10KB, aliased per path

    int tid  = threadIdx.x;
    int lane = tid & 31;
    int w    = tid >> 5;

    if (blockIdx.x < POS_BLOCKS){
        float2* sp = reinterpret_cast<float2*>(smem_raw);   // 1024 float2 = 8KB
        int rg   = blockIdx.x >> 1;
        int half = blockIdx.x & 1;
        int row  = rg * 8 + w;

        float gx = g_gen[row*2], gy = g_gen[row*2 + 1];
        const float2* posv = reinterpret_cast<const float2*>(pos);

        float sps = 0.0f;
        int base = half * (N_PTS / 2);
        for (int tb = base; tb < base + N_PTS/2; tb += PTILE){
            __syncthreads();
            for (int e = tid; e < PTILE; e += 256) sp[e] = posv[tb + e];
            __syncthreads();
            #pragma unroll 8
            for (int j = lane; j < PTILE; j += 32){
                float2 p = sp[j];
                float dx = gx - p.x, dy = gy - p.y;
                float d  = fsqrt_fast(fmaf(dy, dy, dx*dx));
                sps += fexp2_fast(fmaf(d, -KCONST, BIASC));
            }
        }
        #pragma unroll
        for (int o = 16; o; o >>= 1) sps += __shfl_xor_sync(0xffffffffu, sps, o);
        if (lane == 0) g_spos[half][row] = sps;
    } else {
        int t = blockIdx.x - POS_BLOCKS;
        // triangular decode: offset(a) = a*NB - a*(a-1)/2, b = a + t - offset(a)
        int a = (int)(((float)NB + 0.5f) - fsqrt_fast(((float)NB + 0.5f)*((float)NB + 0.5f) - 2.0f*(float)t));
        if (a > NB - 1) a = NB - 1;
        while (a > 0 && a*NB - (a*(a-1))/2 > t) a--;
        while ((a+1)*NB - ((a+1)*a)/2 <= t) a++;
        int b = a + (t - (a*NB - (a*(a-1))/2));

        float2* shr = reinterpret_cast<float2*>(smem_raw);                 // 256 float2 = 2KB
        float (*csum_sh)[SB] = reinterpret_cast<float (*)[SB]>(smem_raw + 512); // 8x256 = 8KB

        const float2* genv = reinterpret_cast<const float2*>(g_gen);

        // stage rows (block a)
        for (int e = tid; e < SB; e += 256) shr[e] = genv[a*SB + e];
        __syncthreads();

        // columns (block b) in registers: lane holds 8 points
        float cx[8], cy[8], csum[8];
        #pragma unroll
        for (int cs = 0; cs < 8; cs++){
            float2 c = genv[b*SB + cs*32 + lane];
            cx[cs] = c.x; cy[cs] = c.y; csum[cs] = 0.0f;
        }

        bool diag = (a == b);

        #pragma unroll 1
        for (int r = 0; r < 32; r++){
            int rloc = w * 32 + r;
            float2 rp = shr[rloc];
            int rl = diag ? rloc : -1;
            float rs = 0.0f;
            #pragma unroll
            for (int cs = 0; cs < 8; cs++){
                float dx = rp.x - cx[cs];
                float dy = rp.y - cy[cs];
                float d  = fsqrt_fast(fmaf(dy, dy, dx*dx));
                float e  = fexp2_fast(fmaf(d, -KCONST, BIASC));
                if (cs*32 + lane == rl) e = 0.0f;
                rs += e;
                csum[cs] += e;
            }
            #pragma unroll
            for (int o = 16; o; o >>= 1) rs += __shfl_xor_sync(0xffffffffu, rs, o);
            if (lane == 0) g_pneg[b][a*SB + rloc] = rs;
        }

        if (!diag){
            #pragma unroll
            for (int cs = 0; cs < 8; cs++) csum_sh[w][cs*32 + lane] = csum[cs];
            __syncthreads();
            for (int c = tid; c < SB; c += 256){
                float s = 0.0f;
                #pragma unroll
                for (int ww = 0; ww < 8; ww++) s += csum_sh[ww][c];
                g_pneg[a][b*SB + c] = s;
            }
        }
    }
}

// ---------------- Final reduce ----------------
__global__ __launch_bounds__(256) void reduce_kernel(float* __restrict__ out)
{
    int i = blockIdx.x * 256 + threadIdx.x;
    float sp = g_spos[0][i] + g_spos[1][i];
    float sn = 0.0f;
    #pragma unroll
    for (int k = 0; k < NB; k++) sn += g_pneg[k][i];
    out[i] = TLN2C * (flog2_fast(sn) - flog2_fast(sp));
}

extern "C" void kernel_launch(void* const* d_in, const int* in_sizes, int n_in,
                              void* d_out, int out_size)
{
    const float* pos = (const float*)d_in[0];
    const float* z   = (const float*)d_in[1];
    const float* W1  = (const float*)d_in[2];  const float* b1 = (const float*)d_in[3];
    const float* W2  = (const float*)d_in[4];  const float* b2 = (const float*)d_in[5];
    const float* W3  = (const float*)d_in[6];  const float* b3 = (const float*)d_in[7];
    const float* W4  = (const float*)d_in[8];  const float* b4 = (const float*)d_in[9];
    const float* W5  = (const float*)d_in[10]; const float* b5 = (const float*)d_in[11];
    (void)in_sizes; (void)n_in; (void)out_size;

    mlp_kernel<<<N_PTS / RT, 128>>>(z, W1, b1, W2, b2, W3, b3, W4, b4, W5, b5);
    energy_kernel<<<POS_BLOCKS + NEG_TILES, 256>>>(pos);
    reduce_kernel<<<N_PTS / 256, 256>>>((float*)d_out);
}

// round 14
// speedup vs baseline: 1.2713x; 1.1517x over previous
#include <cuda_runtime.h>
#include <cuda_bf16.h>
#include <mma.h>
#include <cstdint>

using namespace nvcuda;

#define N_PTS 16384
#define HID   256
#define PTILE 1024
#define SB    256
#define NB    (N_PTS/SB)    // 64
#define POS_BLOCKS 4096
#define NEG_TILES  (NB*(NB+1)/2)   // 2080

#define RB    64            // rows per MLP block
#define APAD  264           // padded A-tile row width (bf16 elems)
#define W_ELEMS (32*256 + 3*256*256)   // 204800

__device__ float g_gen[N_PTS * 2];
__device__ float g_spos[2][N_PTS];
__device__ float g_pneg[NB][N_PTS];
__device__ __align__(16) __nv_bfloat16 g_wh[W_ELEMS];
__device__ __align__(16) __nv_bfloat16 g_wl[W_ELEMS];

__device__ __forceinline__ float fsqrt_fast(float x){ float r; asm("sqrt.approx.f32 %0, %1;" : "=f"(r) : "f"(x)); return r; }
__device__ __forceinline__ float fexp2_fast(float x){ float r; asm("ex2.approx.f32 %0, %1;"  : "=f"(r) : "f"(x)); return r; }
__device__ __forceinline__ float flog2_fast(float x){ float r; asm("lg2.approx.f32 %0, %1;"  : "=f"(r) : "f"(x)); return r; }

#define KCONST 28.853900817779268f
#define TLN2C  0.034657359027997264f
#define BIASC  64.0f

__device__ __forceinline__ float selu_f(float x){
    const float L  = 1.0507009873554805f;
    const float LA = 1.7580993408473766f;
    float e   = fexp2_fast(x * 1.4426950408889634f);
    float neg = LA * (e - 1.0f);
    return x > 0.0f ? L * x : neg;
}

__device__ __forceinline__ void split_bf(float v, __nv_bfloat16& hi, __nv_bfloat16& lo){
    hi = __float2bfloat16(v);
    lo = __float2bfloat16(v - __bfloat162float(hi));
}

// ---------------- weight prep: bf16 hi/lo images, row-major [k][n] ----------------
__global__ __launch_bounds__(256) void prep_kernel(
    const float* __restrict__ W1, const float* __restrict__ W2,
    const float* __restrict__ W3, const float* __restrict__ W4)
{
    int idx = blockIdx.x * 256 + threadIdx.x;
    if (idx >= W_ELEMS) return;
    float v;
    if (idx < 8192)        v = W1[idx];
    else {
        int r = idx - 8192;
        int L = r >> 16;            // 65536 elems per big layer
        int o = r & 65535;
        v = (L == 0) ? W2[o] : (L == 1) ? W3[o] : W4[o];
    }
    __nv_bfloat16 hi, lo;
    split_bf(v, hi, lo);
    g_wh[idx] = hi;
    g_wl[idx] = lo;
}

// ---------------- WMMA MLP ----------------
// 256 threads = 8 warps. Block covers 64 rows. Warp w owns n-cols [w*32, w*32+32).
// A-tiles (bf16 hi/lo) in smem, aliased across layers. B frags from global images.
// 3-product bf16 split: acc += Ah*Bh + Ah*Bl + Al*Bh.
#define SM_AH   0
#define SM_AL   (RB*APAD*2)          // 33792
#define SM_SCR  (2*RB*APAD*2)        // 67584
#define SM_BIAS (SM_SCR + 8*256*4)   // 75776
#define SM_TOT  (SM_BIAS + 1024)     // 76800

__global__ __launch_bounds__(256) void mlp_wmma_kernel(
    const float* __restrict__ z,
    const float* __restrict__ b1, const float* __restrict__ b2,
    const float* __restrict__ b3, const float* __restrict__ b4,
    const float* __restrict__ W5, const float* __restrict__ b5)
{
    extern __shared__ unsigned char sm[];
    __nv_bfloat16 (*Ah)[APAD] = reinterpret_cast<__nv_bfloat16 (*)[APAD]>(sm + SM_AH);
    __nv_bfloat16 (*Al)[APAD] = reinterpret_cast<__nv_bfloat16 (*)[APAD]>(sm + SM_AL);
    float* scratch = reinterpret_cast<float*>(sm + SM_SCR);
    float* bias_sh = reinterpret_cast<float*>(sm + SM_BIAS);

    int tid  = threadIdx.x;
    int lane = tid & 31;
    int w    = tid >> 5;
    int row0 = blockIdx.x * RB;

    // stage z: 64 rows x 32 cols, split hi/lo
    for (int e = tid; e < RB * 32; e += 256){
        int r = e >> 5, c = e & 31;
        __nv_bfloat16 hi, lo;
        split_bf(z[(size_t)(row0 + r) * 32 + c], hi, lo);
        Ah[r][c] = hi; Al[r][c] = lo;
    }
    __syncthreads();

    const int   koff[4]  = {0, 8192, 73728, 139264};
    const int   kin[4]   = {32, 256, 256, 256};
    const float* bias_p[4] = {b1, b2, b3, b4};

    for (int L = 0; L < 4; L++){
        bias_sh[tid] = bias_p[L][tid & 255];
        __syncthreads();

        const __nv_bfloat16* WH = g_wh + koff[L];
        const __nv_bfloat16* WL = g_wl + koff[L];

        wmma::fragment<wmma::accumulator, 16, 16, 16, float> acc[4][2];
        #pragma unroll
        for (int mt = 0; mt < 4; mt++)
            #pragma unroll
            for (int nt = 0; nt < 2; nt++)
                wmma::fill_fragment(acc[mt][nt], 0.0f);

        int nsteps = kin[L] >> 4;
        #pragma unroll 1
        for (int ks = 0; ks < nsteps; ks++){
            wmma::fragment<wmma::matrix_b, 16, 16, 16, __nv_bfloat16, wmma::row_major> bh[2], bl[2];
            #pragma unroll
            for (int nt = 0; nt < 2; nt++){
                const __nv_bfloat16* bp = WH + (size_t)(ks * 16) * 256 + w * 32 + nt * 16;
                const __nv_bfloat16* lp = WL + (size_t)(ks * 16) * 256 + w * 32 + nt * 16;
                wmma::load_matrix_sync(bh[nt], bp, 256);
                wmma::load_matrix_sync(bl[nt], lp, 256);
            }
            #pragma unroll
            for (int mt = 0; mt < 4; mt++){
                wmma::fragment<wmma::matrix_a, 16, 16, 16, __nv_bfloat16, wmma::row_major> ah, al;
                wmma::load_matrix_sync(ah, &Ah[mt * 16][ks * 16], APAD);
                wmma::load_matrix_sync(al, &Al[mt * 16][ks * 16], APAD);
                #pragma unroll
                for (int nt = 0; nt < 2; nt++){
                    wmma::mma_sync(acc[mt][nt], ah, bh[nt], acc[mt][nt]);
                    wmma::mma_sync(acc[mt][nt], ah, bl[nt], acc[mt][nt]);
                    wmma::mma_sync(acc[mt][nt], al, bh[nt], acc[mt][nt]);
                }
            }
        }
        __syncthreads();   // all warps done reading A tiles

        // epilogue: acc -> scratch -> bias+selu -> split back into A tiles
        float* sw = scratch + w * 256;
        #pragma unroll
        for (int mt = 0; mt < 4; mt++){
            #pragma unroll
            for (int nt = 0; nt < 2; nt++){
                wmma::store_matrix_sync(sw, acc[mt][nt], 16, wmma::mem_row_major);
                __syncwarp();
                int n0 = w * 32 + nt * 16;
                #pragma unroll
                for (int i = 0; i < 8; i++){
                    int e = i * 32 + lane;
                    int r = e >> 4, c = e & 15;
                    float v = sw[e] + bias_sh[n0 + c];
                    float h = selu_f(v);
                    __nv_bfloat16 hi, lo;
                    split_bf(h, hi, lo);
                    Ah[mt * 16 + r][n0 + c] = hi;
                    Al[mt * 16 + r][n0 + c] = lo;
                }
                __syncwarp();
            }
        }
        __syncthreads();
    }

    // final 256 -> 2 projection in fp32
    if (tid < RB * 2){
        int r = tid >> 1, d = tid & 1;
        float s = b5[d];
        #pragma unroll 4
        for (int k = 0; k < HID; k++){
            float h = __bfloat162float(Ah[r][k]) + __bfloat162float(Al[r][k]);
            s = fmaf(h, W5[k * 2 + d], s);
        }
        g_gen[(row0 + r) * 2 + d] = s;
    }
}

// ---------------- fused energy kernel (unchanged) ----------------
__global__ __launch_bounds__(256) void energy_kernel(const float* __restrict__ pos)
{
    __shared__ __align__(16) float smem_raw[2560];

    int tid  = threadIdx.x;
    int lane = tid & 31;
    int w    = tid >> 5;

    if (blockIdx.x < POS_BLOCKS){
        float2* sp = reinterpret_cast<float2*>(smem_raw);
        int rg   = blockIdx.x >> 1;
        int half = blockIdx.x & 1;
        int row  = rg * 8 + w;

        float gx = g_gen[row*2], gy = g_gen[row*2 + 1];
        const float2* posv = reinterpret_cast<const float2*>(pos);

        float sps = 0.0f;
        int base = half * (N_PTS / 2);
        for (int tb = base; tb < base + N_PTS/2; tb += PTILE){
            __syncthreads();
            for (int e = tid; e < PTILE; e += 256) sp[e] = posv[tb + e];
            __syncthreads();
            #pragma unroll 8
            for (int j = lane; j < PTILE; j += 32){
                float2 p = sp[j];
                float dx = gx - p.x, dy = gy - p.y;
                float d  = fsqrt_fast(fmaf(dy, dy, dx*dx));
                sps += fexp2_fast(fmaf(d, -KCONST, BIASC));
            }
        }
        #pragma unroll
        for (int o = 16; o; o >>= 1) sps += __shfl_xor_sync(0xffffffffu, sps, o);
        if (lane == 0) g_spos[half][row] = sps;
    } else {
        int t = blockIdx.x - POS_BLOCKS;
        int a = (int)(((float)NB + 0.5f) - fsqrt_fast(((float)NB + 0.5f)*((float)NB + 0.5f) - 2.0f*(float)t));
        if (a > NB - 1) a = NB - 1;
        while (a > 0 && a*NB - (a*(a-1))/2 > t) a--;
        while ((a+1)*NB - ((a+1)*a)/2 <= t) a++;
        int b = a + (t - (a*NB - (a*(a-1))/2));

        float2* shr = reinterpret_cast<float2*>(smem_raw);
        float (*csum_sh)[SB] = reinterpret_cast<float (*)[SB]>(smem_raw + 512);

        const float2* genv = reinterpret_cast<const float2*>(g_gen);

        for (int e = tid; e < SB; e += 256) shr[e] = genv[a*SB + e];
        __syncthreads();

        float cx[8], cy[8], csum[8];
        #pragma unroll
        for (int cs = 0; cs < 8; cs++){
            float2 c = genv[b*SB + cs*32 + lane];
            cx[cs] = c.x; cy[cs] = c.y; csum[cs] = 0.0f;
        }

        bool diag = (a == b);

        #pragma unroll 1
        for (int r = 0; r < 32; r++){
            int rloc = w * 32 + r;
            float2 rp = shr[rloc];
            int rl = diag ? rloc : -1;
            float rs = 0.0f;
            #pragma unroll
            for (int cs = 0; cs < 8; cs++){
                float dx = rp.x - cx[cs];
                float dy = rp.y - cy[cs];
                float d  = fsqrt_fast(fmaf(dy, dy, dx*dx));
                float e  = fexp2_fast(fmaf(d, -KCONST, BIASC));
                if (cs*32 + lane == rl) e = 0.0f;
                rs += e;
                csum[cs] += e;
            }
            #pragma unroll
            for (int o = 16; o; o >>= 1) rs += __shfl_xor_sync(0xffffffffu, rs, o);
            if (lane == 0) g_pneg[b][a*SB + rloc] = rs;
        }

        if (!diag){
            #pragma unroll
            for (int cs = 0; cs < 8; cs++) csum_sh[w][cs*32 + lane] = csum[cs];
            __syncthreads();
            for (int c = tid; c < SB; c += 256){
                float s = 0.0f;
                #pragma unroll
                for (int ww = 0; ww < 8; ww++) s += csum_sh[ww][c];
                g_pneg[a][b*SB + c] = s;
            }
        }
    }
}

__global__ __launch_bounds__(256) void reduce_kernel(float* __restrict__ out)
{
    int i = blockIdx.x * 256 + threadIdx.x;
    float sp = g_spos[0][i] + g_spos[1][i];
    float sn = 0.0f;
    #pragma unroll
    for (int k = 0; k < NB; k++) sn += g_pneg[k][i];
    out[i] = TLN2C * (flog2_fast(sn) - flog2_fast(sp));
}

extern "C" void kernel_launch(void* const* d_in, const int* in_sizes, int n_in,
                              void* d_out, int out_size)
{
    const float* pos = (const float*)d_in[0];
    const float* z   = (const float*)d_in[1];
    const float* W1  = (const float*)d_in[2];  const float* b1 = (const float*)d_in[3];
    const float* W2  = (const float*)d_in[4];  const float* b2 = (const float*)d_in[5];
    const float* W3  = (const float*)d_in[6];  const float* b3 = (const float*)d_in[7];
    const float* W4  = (const float*)d_in[8];  const float* b4 = (const float*)d_in[9];
    const float* W5  = (const float*)d_in[10]; const float* b5 = (const float*)d_in[11];
    (void)in_sizes; (void)n_in; (void)out_size;

    cudaFuncSetAttribute(mlp_wmma_kernel, cudaFuncAttributeMaxDynamicSharedMemorySize, SM_TOT);

    prep_kernel<<<(W_ELEMS + 255) / 256, 256>>>(W1, W2, W3, W4);
    mlp_wmma_kernel<<<N_PTS / RB, 256, SM_TOT>>>(z, b1, b2, b3, b4, W5, b5);
    energy_kernel<<<POS_BLOCKS + NEG_TILES, 256>>>(pos);
    reduce_kernel<<<N_PTS / 256, 256>>>((float*)d_out);
}

// round 15
// speedup vs baseline: 1.4203x; 1.1172x over previous
#include <cuda_runtime.h>
#include <cuda_fp16.h>
#include <mma.h>
#include <cstdint>

using namespace nvcuda;

#define N_PTS 16384
#define HID   256
#define PTILE 1024
#define SB    256
#define NB    (N_PTS/SB)    // 64
#define POS_BLOCKS 4096
#define NEG_TILES  (NB*(NB+1)/2)   // 2080

#define RB    64            // rows per MLP block
#define APAD  264           // padded A-tile row width (half elems)
#define W_ELEMS (32*256 + 3*256*256)   // 204800

__device__ float g_gen[N_PTS * 2];
__device__ float g_spos[2][N_PTS];
__device__ float g_pneg[NB][N_PTS];
__device__ __align__(16) __half g_wh[W_ELEMS];

__device__ __forceinline__ float fsqrt_fast(float x){ float r; asm("sqrt.approx.f32 %0, %1;" : "=f"(r) : "f"(x)); return r; }
__device__ __forceinline__ float fexp2_fast(float x){ float r; asm("ex2.approx.f32 %0, %1;"  : "=f"(r) : "f"(x)); return r; }
__device__ __forceinline__ float flog2_fast(float x){ float r; asm("lg2.approx.f32 %0, %1;"  : "=f"(r) : "f"(x)); return r; }

#define KCONST 28.853900817779268f
#define TLN2C  0.034657359027997264f
#define BIASC  64.0f

__device__ __forceinline__ float selu_f(float x){
    const float L  = 1.0507009873554805f;
    const float LA = 1.7580993408473766f;
    float e   = fexp2_fast(x * 1.4426950408889634f);
    float neg = LA * (e - 1.0f);
    return x > 0.0f ? L * x : neg;
}

__device__ __forceinline__ void split_h(float v, __half& hi, __half& lo){
    hi = __float2half_rn(v);
    lo = __float2half_rn(v - __half2float(hi));
}

// ---------------- weight prep: fp16 image, row-major [k][n] ----------------
__global__ __launch_bounds__(256) void prep_kernel(
    const float* __restrict__ W1, const float* __restrict__ W2,
    const float* __restrict__ W3, const float* __restrict__ W4)
{
    int idx = blockIdx.x * 256 + threadIdx.x;
    if (idx >= W_ELEMS) return;
    float v;
    if (idx < 8192)        v = W1[idx];
    else {
        int r = idx - 8192;
        int L = r >> 16;            // 65536 elems per big layer
        int o = r & 65535;
        v = (L == 0) ? W2[o] : (L == 1) ? W3[o] : W4[o];
    }
    g_wh[idx] = __float2half_rn(v);
}

// ---------------- WMMA MLP (fp16, 2-product activation split) ----------------
// 256 threads = 8 warps. Block covers 64 rows. Warp w owns n-cols [w*32, w*32+32).
// Activations split hi/lo fp16 (exact to ~2^-22); weights single fp16.
// acc += Ah*Bh + Al*Bh  (one B fragment shared by both products).
#define SM_AH   0
#define SM_AL   (RB*APAD*2)          // 33792
#define SM_SCR  (2*RB*APAD*2)        // 67584
#define SM_BIAS (SM_SCR + 8*256*4)   // 75776
#define SM_TOT  (SM_BIAS + 1024)     // 76800

__global__ __launch_bounds__(256) void mlp_wmma_kernel(
    const float* __restrict__ z,
    const float* __restrict__ b1, const float* __restrict__ b2,
    const float* __restrict__ b3, const float* __restrict__ b4,
    const float* __restrict__ W5, const float* __restrict__ b5)
{
    extern __shared__ unsigned char sm[];
    __half (*Ah)[APAD] = reinterpret_cast<__half (*)[APAD]>(sm + SM_AH);
    __half (*Al)[APAD] = reinterpret_cast<__half (*)[APAD]>(sm + SM_AL);
    float* scratch = reinterpret_cast<float*>(sm + SM_SCR);
    float* bias_sh = reinterpret_cast<float*>(sm + SM_BIAS);

    int tid  = threadIdx.x;
    int lane = tid & 31;
    int w    = tid >> 5;
    int row0 = blockIdx.x * RB;

    // stage z: 64 rows x 32 cols, split hi/lo
    for (int e = tid; e < RB * 32; e += 256){
        int r = e >> 5, c = e & 31;
        __half hi, lo;
        split_h(z[(size_t)(row0 + r) * 32 + c], hi, lo);
        Ah[r][c] = hi; Al[r][c] = lo;
    }
    __syncthreads();

    const int   koff[4]  = {0, 8192, 73728, 139264};
    const int   kin[4]   = {32, 256, 256, 256};
    const float* bias_p[4] = {b1, b2, b3, b4};

    for (int L = 0; L < 4; L++){
        bias_sh[tid] = bias_p[L][tid & 255];
        __syncthreads();

        const __half* WH = g_wh + koff[L];

        wmma::fragment<wmma::accumulator, 16, 16, 16, float> acc[4][2];
        #pragma unroll
        for (int mt = 0; mt < 4; mt++)
            #pragma unroll
            for (int nt = 0; nt < 2; nt++)
                wmma::fill_fragment(acc[mt][nt], 0.0f);

        int nsteps = kin[L] >> 4;
        #pragma unroll 1
        for (int ks = 0; ks < nsteps; ks++){
            wmma::fragment<wmma::matrix_b, 16, 16, 16, __half, wmma::row_major> bh[2];
            #pragma unroll
            for (int nt = 0; nt < 2; nt++){
                const __half* bp = WH + (size_t)(ks * 16) * 256 + w * 32 + nt * 16;
                wmma::load_matrix_sync(bh[nt], bp, 256);
            }
            #pragma unroll
            for (int mt = 0; mt < 4; mt++){
                wmma::fragment<wmma::matrix_a, 16, 16, 16, __half, wmma::row_major> ah, al;
                wmma::load_matrix_sync(ah, &Ah[mt * 16][ks * 16], APAD);
                wmma::load_matrix_sync(al, &Al[mt * 16][ks * 16], APAD);
                #pragma unroll
                for (int nt = 0; nt < 2; nt++){
                    wmma::mma_sync(acc[mt][nt], ah, bh[nt], acc[mt][nt]);
                    wmma::mma_sync(acc[mt][nt], al, bh[nt], acc[mt][nt]);
                }
            }
        }
        __syncthreads();   // all warps done reading A tiles

        // epilogue: acc -> scratch -> bias+selu -> split back into A tiles
        float* sw = scratch + w * 256;
        #pragma unroll
        for (int mt = 0; mt < 4; mt++){
            #pragma unroll
            for (int nt = 0; nt < 2; nt++){
                wmma::store_matrix_sync(sw, acc[mt][nt], 16, wmma::mem_row_major);
                __syncwarp();
                int n0 = w * 32 + nt * 16;
                #pragma unroll
                for (int i = 0; i < 8; i++){
                    int e = i * 32 + lane;
                    int r = e >> 4, c = e & 15;
                    float v = sw[e] + bias_sh[n0 + c];
                    float h = selu_f(v);
                    __half hi, lo;
                    split_h(h, hi, lo);
                    Ah[mt * 16 + r][n0 + c] = hi;
                    Al[mt * 16 + r][n0 + c] = lo;
                }
                __syncwarp();
            }
        }
        __syncthreads();
    }

    // final 256 -> 2 projection in fp32
    if (tid < RB * 2){
        int r = tid >> 1, d = tid & 1;
        float s = b5[d];
        #pragma unroll 4
        for (int k = 0; k < HID; k++){
            float h = __half2float(Ah[r][k]) + __half2float(Al[r][k]);
            s = fmaf(h, W5[k * 2 + d], s);
        }
        g_gen[(row0 + r) * 2 + d] = s;
    }
}

// ---------------- fused energy kernel (unchanged) ----------------
__global__ __launch_bounds__(256) void energy_kernel(const float* __restrict__ pos)
{
    __shared__ __align__(16) float smem_raw[2560];

    int tid  = threadIdx.x;
    int lane = tid & 31;
    int w    = tid >> 5;

    if (blockIdx.x < POS_BLOCKS){
        float2* sp = reinterpret_cast<float2*>(smem_raw);
        int rg   = blockIdx.x >> 1;
        int half = blockIdx.x & 1;
        int row  = rg * 8 + w;

        float gx = g_gen[row*2], gy = g_gen[row*2 + 1];
        const float2* posv = reinterpret_cast<const float2*>(pos);

        float sps = 0.0f;
        int base = half * (N_PTS / 2);
        for (int tb = base; tb < base + N_PTS/2; tb += PTILE){
            __syncthreads();
            for (int e = tid; e < PTILE; e += 256) sp[e] = posv[tb + e];
            __syncthreads();
            #pragma unroll 8
            for (int j = lane; j < PTILE; j += 32){
                float2 p = sp[j];
                float dx = gx - p.x, dy = gy - p.y;
                float d  = fsqrt_fast(fmaf(dy, dy, dx*dx));
                sps += fexp2_fast(fmaf(d, -KCONST, BIASC));
            }
        }
        #pragma unroll
        for (int o = 16; o; o >>= 1) sps += __shfl_xor_sync(0xffffffffu, sps, o);
        if (lane == 0) g_spos[half][row] = sps;
    } else {
        int t = blockIdx.x - POS_BLOCKS;
        int a = (int)(((float)NB + 0.5f) - fsqrt_fast(((float)NB + 0.5f)*((float)NB + 0.5f) - 2.0f*(float)t));
        if (a > NB - 1) a = NB - 1;
        while (a > 0 && a*NB - (a*(a-1))/2 > t) a--;
        while ((a+1)*NB - ((a+1)*a)/2 <= t) a++;
        int b = a + (t - (a*NB - (a*(a-1))/2));

        float2* shr = reinterpret_cast<float2*>(smem_raw);
        float (*csum_sh)[SB] = reinterpret_cast<float (*)[SB]>(smem_raw + 512);

        const float2* genv = reinterpret_cast<const float2*>(g_gen);

        for (int e = tid; e < SB; e += 256) shr[e] = genv[a*SB + e];
        __syncthreads();

        float cx[8], cy[8], csum[8];
        #pragma unroll
        for (int cs = 0; cs < 8; cs++){
            float2 c = genv[b*SB + cs*32 + lane];
            cx[cs] = c.x; cy[cs] = c.y; csum[cs] = 0.0f;
        }

        bool diag = (a == b);

        #pragma unroll 1
        for (int r = 0; r < 32; r++){
            int rloc = w * 32 + r;
            float2 rp = shr[rloc];
            int rl = diag ? rloc : -1;
            float rs = 0.0f;
            #pragma unroll
            for (int cs = 0; cs < 8; cs++){
                float dx = rp.x - cx[cs];
                float dy = rp.y - cy[cs];
                float d  = fsqrt_fast(fmaf(dy, dy, dx*dx));
                float e  = fexp2_fast(fmaf(d, -KCONST, BIASC));
                if (cs*32 + lane == rl) e = 0.0f;
                rs += e;
                csum[cs] += e;
            }
            #pragma unroll
            for (int o = 16; o; o >>= 1) rs += __shfl_xor_sync(0xffffffffu, rs, o);
            if (lane == 0) g_pneg[b][a*SB + rloc] = rs;
        }

        if (!diag){
            #pragma unroll
            for (int cs = 0; cs < 8; cs++) csum_sh[w][cs*32 + lane] = csum[cs];
            __syncthreads();
            for (int c = tid; c < SB; c += 256){
                float s = 0.0f;
                #pragma unroll
                for (int ww = 0; ww < 8; ww++) s += csum_sh[ww][c];
                g_pneg[a][b*SB + c] = s;
            }
        }
    }
}

__global__ __launch_bounds__(256) void reduce_kernel(float* __restrict__ out)
{
    int i = blockIdx.x * 256 + threadIdx.x;
    float sp = g_spos[0][i] + g_spos[1][i];
    float sn = 0.0f;
    #pragma unroll
    for (int k = 0; k < NB; k++) sn += g_pneg[k][i];
    out[i] = TLN2C * (flog2_fast(sn) - flog2_fast(sp));
}

extern "C" void kernel_launch(void* const* d_in, const int* in_sizes, int n_in,
                              void* d_out, int out_size)
{
    const float* pos = (const float*)d_in[0];
    const float* z   = (const float*)d_in[1];
    const float* W1  = (const float*)d_in[2];  const float* b1 = (const float*)d_in[3];
    const float* W2  = (const float*)d_in[4];  const float* b2 = (const float*)d_in[5];
    const float* W3  = (const float*)d_in[6];  const float* b3 = (const float*)d_in[7];
    const float* W4  = (const float*)d_in[8];  const float* b4 = (const float*)d_in[9];
    const float* W5  = (const float*)d_in[10]; const float* b5 = (const float*)d_in[11];
    (void)in_sizes; (void)n_in; (void)out_size;

    cudaFuncSetAttribute(mlp_wmma_kernel, cudaFuncAttributeMaxDynamicSharedMemorySize, SM_TOT);

    prep_kernel<<<(W_ELEMS + 255) / 256, 256>>>(W1, W2, W3, W4);
    mlp_wmma_kernel<<<N_PTS / RB, 256, SM_TOT>>>(z, b1, b2, b3, b4, W5, b5);
    energy_kernel<<<POS_BLOCKS + NEG_TILES, 256>>>(pos);
    reduce_kernel<<<N_PTS / 256, 256>>>((float*)d_out);
}

// round 16
// speedup vs baseline: 1.4668x; 1.0328x over previous
#include <cuda_runtime.h>
#include <cuda_fp16.h>
#include <mma.h>
#include <cstdint>

using namespace nvcuda;

#define N_PTS 16384
#define HID   256
#define PTILE 1024
#define SB    256
#define NB    (N_PTS/SB)    // 64
#define POS_BLOCKS 4096
#define NEG_TILES  (NB*(NB+1)/2)   // 2080

#define RB    64            // rows per MLP block
#define APAD  264           // padded A-tile row width (half elems)
#define W_ELEMS (32*256 + 3*256*256)   // 204800

__device__ float g_gen[N_PTS * 2];
__device__ float g_spos[2][N_PTS];
__device__ float g_pneg[NB][N_PTS];
__device__ __align__(16) __half g_wh[W_ELEMS];

__device__ __forceinline__ float fsqrt_fast(float x){ float r; asm("sqrt.approx.f32 %0, %1;" : "=f"(r) : "f"(x)); return r; }
__device__ __forceinline__ float fexp2_fast(float x){ float r; asm("ex2.approx.f32 %0, %1;"  : "=f"(r) : "f"(x)); return r; }
__device__ __forceinline__ float flog2_fast(float x){ float r; asm("lg2.approx.f32 %0, %1;"  : "=f"(r) : "f"(x)); return r; }

#define KCONST 28.853900817779268f
#define TLN2C  0.034657359027997264f
#define BIASC  64.0f

__device__ __forceinline__ float selu_f(float x){
    const float L  = 1.0507009873554805f;
    const float LA = 1.7580993408473766f;
    float e   = fexp2_fast(x * 1.4426950408889634f);
    float neg = LA * (e - 1.0f);
    return x > 0.0f ? L * x : neg;
}

__device__ __forceinline__ void split_h(float v, __half& hi, __half& lo){
    hi = __float2half_rn(v);
    lo = __float2half_rn(v - __half2float(hi));
}

// ---------------- weight prep: fp16 image, row-major [k][n] ----------------
__global__ __launch_bounds__(256) void prep_kernel(
    const float* __restrict__ W1, const float* __restrict__ W2,
    const float* __restrict__ W3, const float* __restrict__ W4)
{
    int idx = blockIdx.x * 256 + threadIdx.x;
    if (idx >= W_ELEMS) return;
    float v;
    if (idx < 8192)        v = W1[idx];
    else {
        int r = idx - 8192;
        int L = r >> 16;            // 65536 elems per big layer
        int o = r & 65535;
        v = (L == 0) ? W2[o] : (L == 1) ? W3[o] : W4[o];
    }
    g_wh[idx] = __float2half_rn(v);
}

// ---------------- WMMA MLP (fp16, single product) ----------------
// 256 threads = 8 warps. Block covers 64 rows. Warp w owns n-cols [w*32, w*32+32).
// Hidden layers: acc += Ah*Bh (single MMA per tile). The layer-4 epilogue
// additionally writes the fp16 residual (Al) so the final fp32 projection
// sees activations exact to ~2^-22.
#define SM_AH   0
#define SM_AL   (RB*APAD*2)          // 33792
#define SM_SCR  (2*RB*APAD*2)        // 67584
#define SM_BIAS (SM_SCR + 8*256*4)   // 75776
#define SM_TOT  (SM_BIAS + 1024)     // 76800

__global__ __launch_bounds__(256) void mlp_wmma_kernel(
    const float* __restrict__ z,
    const float* __restrict__ b1, const float* __restrict__ b2,
    const float* __restrict__ b3, const float* __restrict__ b4,
    const float* __restrict__ W5, const float* __restrict__ b5)
{
    extern __shared__ unsigned char sm[];
    __half (*Ah)[APAD] = reinterpret_cast<__half (*)[APAD]>(sm + SM_AH);
    __half (*Al)[APAD] = reinterpret_cast<__half (*)[APAD]>(sm + SM_AL);
    float* scratch = reinterpret_cast<float*>(sm + SM_SCR);
    float* bias_sh = reinterpret_cast<float*>(sm + SM_BIAS);

    int tid  = threadIdx.x;
    int lane = tid & 31;
    int w    = tid >> 5;
    int row0 = blockIdx.x * RB;

    // stage z: 64 rows x 32 cols (fp16)
    for (int e = tid; e < RB * 32; e += 256){
        int r = e >> 5, c = e & 31;
        Ah[r][c] = __float2half_rn(z[(size_t)(row0 + r) * 32 + c]);
    }
    __syncthreads();

    const int   koff[4]  = {0, 8192, 73728, 139264};
    const int   kin[4]   = {32, 256, 256, 256};
    const float* bias_p[4] = {b1, b2, b3, b4};

    for (int L = 0; L < 4; L++){
        bias_sh[tid] = bias_p[L][tid & 255];
        __syncthreads();

        const __half* WH = g_wh + koff[L];

        wmma::fragment<wmma::accumulator, 16, 16, 16, float> acc[4][2];
        #pragma unroll
        for (int mt = 0; mt < 4; mt++)
            #pragma unroll
            for (int nt = 0; nt < 2; nt++)
                wmma::fill_fragment(acc[mt][nt], 0.0f);

        int nsteps = kin[L] >> 4;
        #pragma unroll 1
        for (int ks = 0; ks < nsteps; ks++){
            wmma::fragment<wmma::matrix_b, 16, 16, 16, __half, wmma::row_major> bh[2];
            #pragma unroll
            for (int nt = 0; nt < 2; nt++){
                const __half* bp = WH + (size_t)(ks * 16) * 256 + w * 32 + nt * 16;
                wmma::load_matrix_sync(bh[nt], bp, 256);
            }
            #pragma unroll
            for (int mt = 0; mt < 4; mt++){
                wmma::fragment<wmma::matrix_a, 16, 16, 16, __half, wmma::row_major> ah;
                wmma::load_matrix_sync(ah, &Ah[mt * 16][ks * 16], APAD);
                #pragma unroll
                for (int nt = 0; nt < 2; nt++)
                    wmma::mma_sync(acc[mt][nt], ah, bh[nt], acc[mt][nt]);
            }
        }
        __syncthreads();   // all warps done reading A tiles

        // epilogue: acc -> scratch -> bias+selu -> back into A tiles
        bool last = (L == 3);
        float* sw = scratch + w * 256;
        #pragma unroll
        for (int mt = 0; mt < 4; mt++){
            #pragma unroll
            for (int nt = 0; nt < 2; nt++){
                wmma::store_matrix_sync(sw, acc[mt][nt], 16, wmma::mem_row_major);
                __syncwarp();
                int n0 = w * 32 + nt * 16;
                #pragma unroll
                for (int i = 0; i < 8; i++){
                    int e = i * 32 + lane;
                    int r = e >> 4, c = e & 15;
                    float v = sw[e] + bias_sh[n0 + c];
                    float h = selu_f(v);
                    if (last){
                        __half hi, lo;
                        split_h(h, hi, lo);
                        Ah[mt * 16 + r][n0 + c] = hi;
                        Al[mt * 16 + r][n0 + c] = lo;
                    } else {
                        Ah[mt * 16 + r][n0 + c] = __float2half_rn(h);
                    }
                }
                __syncwarp();
            }
        }
        __syncthreads();
    }

    // final 256 -> 2 projection in fp32 (hi+lo reconstruction)
    if (tid < RB * 2){
        int r = tid >> 1, d = tid & 1;
        float s = b5[d];
        #pragma unroll 4
        for (int k = 0; k < HID; k++){
            float h = __half2float(Ah[r][k]) + __half2float(Al[r][k]);
            s = fmaf(h, W5[k * 2 + d], s);
        }
        g_gen[(row0 + r) * 2 + d] = s;
    }
}

// ---------------- fused energy kernel (unchanged) ----------------
__global__ __launch_bounds__(256) void energy_kernel(const float* __restrict__ pos)
{
    __shared__ __align__(16) float smem_raw[2560];

    int tid  = threadIdx.x;
    int lane = tid & 31;
    int w    = tid >> 5;

    if (blockIdx.x < POS_BLOCKS){
        float2* sp = reinterpret_cast<float2*>(smem_raw);
        int rg   = blockIdx.x >> 1;
        int half = blockIdx.x & 1;
        int row  = rg * 8 + w;

        float gx = g_gen[row*2], gy = g_gen[row*2 + 1];
        const float2* posv = reinterpret_cast<const float2*>(pos);

        float sps = 0.0f;
        int base = half * (N_PTS / 2);
        for (int tb = base; tb < base + N_PTS/2; tb += PTILE){
            __syncthreads();
            for (int e = tid; e < PTILE; e += 256) sp[e] = posv[tb + e];
            __syncthreads();
            #pragma unroll 8
            for (int j = lane; j < PTILE; j += 32){
                float2 p = sp[j];
                float dx = gx - p.x, dy = gy - p.y;
                float d  = fsqrt_fast(fmaf(dy, dy, dx*dx));
                sps += fexp2_fast(fmaf(d, -KCONST, BIASC));
            }
        }
        #pragma unroll
        for (int o = 16; o; o >>= 1) sps += __shfl_xor_sync(0xffffffffu, sps, o);
        if (lane == 0) g_spos[half][row] = sps;
    } else {
        int t = blockIdx.x - POS_BLOCKS;
        int a = (int)(((float)NB + 0.5f) - fsqrt_fast(((float)NB + 0.5f)*((float)NB + 0.5f) - 2.0f*(float)t));
        if (a > NB - 1) a = NB - 1;
        while (a > 0 && a*NB - (a*(a-1))/2 > t) a--;
        while ((a+1)*NB - ((a+1)*a)/2 <= t) a++;
        int b = a + (t - (a*NB - (a*(a-1))/2));

        float2* shr = reinterpret_cast<float2*>(smem_raw);
        float (*csum_sh)[SB] = reinterpret_cast<float (*)[SB]>(smem_raw + 512);

        const float2* genv = reinterpret_cast<const float2*>(g_gen);

        for (int e = tid; e < SB; e += 256) shr[e] = genv[a*SB + e];
        __syncthreads();

        float cx[8], cy[8], csum[8];
        #pragma unroll
        for (int cs = 0; cs < 8; cs++){
            float2 c = genv[b*SB + cs*32 + lane];
            cx[cs] = c.x; cy[cs] = c.y; csum[cs] = 0.0f;
        }

        bool diag = (a == b);

        #pragma unroll 1
        for (int r = 0; r < 32; r++){
            int rloc = w * 32 + r;
            float2 rp = shr[rloc];
            int rl = diag ? rloc : -1;
            float rs = 0.0f;
            #pragma unroll
            for (int cs = 0; cs < 8; cs++){
                float dx = rp.x - cx[cs];
                float dy = rp.y - cy[cs];
                float d  = fsqrt_fast(fmaf(dy, dy, dx*dx));
                float e  = fexp2_fast(fmaf(d, -KCONST, BIASC));
                if (cs*32 + lane == rl) e = 0.0f;
                rs += e;
                csum[cs] += e;
            }
            #pragma unroll
            for (int o = 16; o; o >>= 1) rs += __shfl_xor_sync(0xffffffffu, rs, o);
            if (lane == 0) g_pneg[b][a*SB + rloc] = rs;
        }

        if (!diag){
            #pragma unroll
            for (int cs = 0; cs < 8; cs++) csum_sh[w][cs*32 + lane] = csum[cs];
            __syncthreads();
            for (int c = tid; c < SB; c += 256){
                float s = 0.0f;
                #pragma unroll
                for (int ww = 0; ww < 8; ww++) s += csum_sh[ww][c];
                g_pneg[a][b*SB + c] = s;
            }
        }
    }
}

__global__ __launch_bounds__(256) void reduce_kernel(float* __restrict__ out)
{
    int i = blockIdx.x * 256 + threadIdx.x;
    float sp = g_spos[0][i] + g_spos[1][i];
    float sn = 0.0f;
    #pragma unroll
    for (int k = 0; k < NB; k++) sn += g_pneg[k][i];
    out[i] = TLN2C * (flog2_fast(sn) - flog2_fast(sp));
}

extern "C" void kernel_launch(void* const* d_in, const int* in_sizes, int n_in,
                              void* d_out, int out_size)
{
    const float* pos = (const float*)d_in[0];
    const float* z   = (const float*)d_in[1];
    const float* W1  = (const float*)d_in[2];  const float* b1 = (const float*)d_in[3];
    const float* W2  = (const float*)d_in[4];  const float* b2 = (const float*)d_in[5];
    const float* W3  = (const float*)d_in[6];  const float* b3 = (const float*)d_in[7];
    const float* W4  = (const float*)d_in[8];  const float* b4 = (const float*)d_in[9];
    const float* W5  = (const float*)d_in[10]; const float* b5 = (const float*)d_in[11];
    (void)in_sizes; (void)n_in; (void)out_size;

    cudaFuncSetAttribute(mlp_wmma_kernel, cudaFuncAttributeMaxDynamicSharedMemorySize, SM_TOT);

    prep_kernel<<<(W_ELEMS + 255) / 256, 256>>>(W1, W2, W3, W4);
    mlp_wmma_kernel<<<N_PTS / RB, 256, SM_TOT>>>(z, b1, b2, b3, b4, W5, b5);
    energy_kernel<<<POS_BLOCKS + NEG_TILES, 256>>>(pos);
    reduce_kernel<<<N_PTS / 256, 256>>>((float*)d_out);
}

// round 17
// speedup vs baseline: 1.4734x; 1.0044x over previous
#include <cuda_runtime.h>
#include <cuda_fp16.h>
#include <mma.h>
#include <cstdint>

using namespace nvcuda;

#define N_PTS 16384
#define HID   256
#define SB    256
#define NB    (N_PTS/SB)    // 64
#define POS_BLOCKS (NB*NB)          // 4096 pos tiles (64x64)
#define NEG_TILES  (NB*(NB+1)/2)    // 2080

#define RB    128           // rows per MLP block
#define APAD  264           // padded A-tile row width (half elems)
#define W_ELEMS (32*256 + 3*256*256)   // 204800

__device__ float g_gen[N_PTS * 2];
__device__ float g_ppos[NB][N_PTS];   // partial pos sums: [colBlock][row]
__device__ float g_pneg[NB][N_PTS];   // partial neg sums: [originColBlock][row]
__device__ __align__(16) __half g_wh[W_ELEMS];

__device__ __forceinline__ float fsqrt_fast(float x){ float r; asm("sqrt.approx.f32 %0, %1;" : "=f"(r) : "f"(x)); return r; }
__device__ __forceinline__ float fexp2_fast(float x){ float r; asm("ex2.approx.f32 %0, %1;"  : "=f"(r) : "f"(x)); return r; }
__device__ __forceinline__ float flog2_fast(float x){ float r; asm("lg2.approx.f32 %0, %1;"  : "=f"(r) : "f"(x)); return r; }

#define KCONST 28.853900817779268f
#define TLN2C  0.034657359027997264f
#define BIASC  64.0f

__device__ __forceinline__ float selu_f(float x){
    const float L  = 1.0507009873554805f;
    const float LA = 1.7580993408473766f;
    float e   = fexp2_fast(x * 1.4426950408889634f);
    float neg = LA * (e - 1.0f);
    return x > 0.0f ? L * x : neg;
}

// ---------------- weight prep: fp16 image, row-major [k][n] ----------------
__global__ __launch_bounds__(256) void prep_kernel(
    const float* __restrict__ W1, const float* __restrict__ W2,
    const float* __restrict__ W3, const float* __restrict__ W4)
{
    int idx = blockIdx.x * 256 + threadIdx.x;
    if (idx >= W_ELEMS) return;
    float v;
    if (idx < 8192)        v = W1[idx];
    else {
        int r = idx - 8192;
        int L = r >> 16;
        int o = r & 65535;
        v = (L == 0) ? W2[o] : (L == 1) ? W3[o] : W4[o];
    }
    g_wh[idx] = __float2half_rn(v);
}

// ---------------- WMMA MLP (fp16, single product, RB=128) ----------------
// 256 threads = 8 warps, block covers 128 rows (one wave: 128 blocks).
// Warp w owns n-cols [w*32, w*32+32). acc += Ah*Bh.
#define SM_AH   0
#define SM_SCR  (RB*APAD*2)          // 67584
#define SM_BIAS (SM_SCR + 8*256*4)   // 75776
#define SM_TOT  (SM_BIAS + 1024)     // 76800

__global__ __launch_bounds__(256) void mlp_wmma_kernel(
    const float* __restrict__ z,
    const float* __restrict__ b1, const float* __restrict__ b2,
    const float* __restrict__ b3, const float* __restrict__ b4,
    const float* __restrict__ W5, const float* __restrict__ b5)
{
    extern __shared__ unsigned char sm[];
    __half (*Ah)[APAD] = reinterpret_cast<__half (*)[APAD]>(sm + SM_AH);
    float* scratch = reinterpret_cast<float*>(sm + SM_SCR);
    float* bias_sh = reinterpret_cast<float*>(sm + SM_BIAS);

    int tid  = threadIdx.x;
    int lane = tid & 31;
    int w    = tid >> 5;
    int row0 = blockIdx.x * RB;

    // stage z: 128 rows x 32 cols (fp16)
    for (int e = tid; e < RB * 32; e += 256){
        int r = e >> 5, c = e & 31;
        Ah[r][c] = __float2half_rn(z[(size_t)(row0 + r) * 32 + c]);
    }
    __syncthreads();

    const int   koff[4]  = {0, 8192, 73728, 139264};
    const int   kin[4]   = {32, 256, 256, 256};
    const float* bias_p[4] = {b1, b2, b3, b4};

    for (int L = 0; L < 4; L++){
        bias_sh[tid] = bias_p[L][tid & 255];
        __syncthreads();

        const __half* WH = g_wh + koff[L];

        wmma::fragment<wmma::accumulator, 16, 16, 16, float> acc[8][2];
        #pragma unroll
        for (int mt = 0; mt < 8; mt++)
            #pragma unroll
            for (int nt = 0; nt < 2; nt++)
                wmma::fill_fragment(acc[mt][nt], 0.0f);

        int nsteps = kin[L] >> 4;
        #pragma unroll 1
        for (int ks = 0; ks < nsteps; ks++){
            wmma::fragment<wmma::matrix_b, 16, 16, 16, __half, wmma::row_major> bh[2];
            #pragma unroll
            for (int nt = 0; nt < 2; nt++){
                const __half* bp = WH + (size_t)(ks * 16) * 256 + w * 32 + nt * 16;
                wmma::load_matrix_sync(bh[nt], bp, 256);
            }
            #pragma unroll
            for (int mt = 0; mt < 8; mt++){
                wmma::fragment<wmma::matrix_a, 16, 16, 16, __half, wmma::row_major> ah;
                wmma::load_matrix_sync(ah, &Ah[mt * 16][ks * 16], APAD);
                #pragma unroll
                for (int nt = 0; nt < 2; nt++)
                    wmma::mma_sync(acc[mt][nt], ah, bh[nt], acc[mt][nt]);
            }
        }
        __syncthreads();   // all warps done reading A tiles

        // epilogue: acc -> scratch -> bias+selu -> back into A tiles
        float* sw = scratch + w * 256;
        #pragma unroll
        for (int mt = 0; mt < 8; mt++){
            #pragma unroll
            for (int nt = 0; nt < 2; nt++){
                wmma::store_matrix_sync(sw, acc[mt][nt], 16, wmma::mem_row_major);
                __syncwarp();
                int n0 = w * 32 + nt * 16;
                #pragma unroll
                for (int i = 0; i < 8; i++){
                    int e = i * 32 + lane;
                    int r = e >> 4, c = e & 15;
                    float v = sw[e] + bias_sh[n0 + c];
                    Ah[mt * 16 + r][n0 + c] = __float2half_rn(selu_f(v));
                }
                __syncwarp();
            }
        }
        __syncthreads();
    }

    // final 256 -> 2 projection in fp32
    {
        int r = tid >> 1, d = tid & 1;
        float s = b5[d];
        #pragma unroll 4
        for (int k = 0; k < HID; k++){
            float h = __half2float(Ah[r][k]);
            s = fmaf(h, W5[k * 2 + d], s);
        }
        g_gen[(row0 + r) * 2 + d] = s;
    }
}

// ---------------- fused energy kernel ----------------
// Pos blocks [0, 4096): tile (rb, cb) of 256 gen rows x 256 pos cols.
//   Rows staged in shared; 8 pos cols/lane in registers; row sums ->
//   g_ppos[cb][row] (single writer).
// Neg blocks: triangular tile (a<=b) over the symmetric gen-gen matrix;
//   off-diag tiles credit both row and column sums.
// Fixed bias 64 inside exp2 cancels exactly in the final pos/neg log ratio.
__global__ __launch_bounds__(256) void energy_kernel(const float* __restrict__ pos)
{
    __shared__ __align__(16) float smem_raw[2560];

    int tid  = threadIdx.x;
    int lane = tid & 31;
    int w    = tid >> 5;

    if (blockIdx.x < POS_BLOCKS){
        int rb = blockIdx.x >> 6;
        int cb = blockIdx.x & 63;

        float2* shr = reinterpret_cast<float2*>(smem_raw);   // 256 gen rows
        const float2* genv = reinterpret_cast<const float2*>(g_gen);
        const float2* posv = reinterpret_cast<const float2*>(pos);

        for (int e = tid; e < SB; e += 256) shr[e] = genv[rb*SB + e];
        __syncthreads();

        float cx[8], cy[8];
        #pragma unroll
        for (int cs = 0; cs < 8; cs++){
            float2 c = posv[cb*SB + cs*32 + lane];
            cx[cs] = c.x; cy[cs] = c.y;
        }

        #pragma unroll 1
        for (int r = 0; r < 32; r++){
            int rloc = w * 32 + r;
            float2 rp = shr[rloc];
            float rs = 0.0f;
            #pragma unroll
            for (int cs = 0; cs < 8; cs++){
                float dx = rp.x - cx[cs];
                float dy = rp.y - cy[cs];
                float d  = fsqrt_fast(fmaf(dy, dy, dx*dx));
                rs += fexp2_fast(fmaf(d, -KCONST, BIASC));
            }
            #pragma unroll
            for (int o = 16; o; o >>= 1) rs += __shfl_xor_sync(0xffffffffu, rs, o);
            if (lane == 0) g_ppos[cb][rb*SB + rloc] = rs;
        }
    } else {
        int t = blockIdx.x - POS_BLOCKS;
        int a = (int)(((float)NB + 0.5f) - fsqrt_fast(((float)NB + 0.5f)*((float)NB + 0.5f) - 2.0f*(float)t));
        if (a > NB - 1) a = NB - 1;
        while (a > 0 && a*NB - (a*(a-1))/2 > t) a--;
        while ((a+1)*NB - ((a+1)*a)/2 <= t) a++;
        int b = a + (t - (a*NB - (a*(a-1))/2));

        float2* shr = reinterpret_cast<float2*>(smem_raw);
        float (*csum_sh)[SB] = reinterpret_cast<float (*)[SB]>(smem_raw + 512);

        const float2* genv = reinterpret_cast<const float2*>(g_gen);

        for (int e = tid; e < SB; e += 256) shr[e] = genv[a*SB + e];
        __syncthreads();

        float cx[8], cy[8], csum[8];
        #pragma unroll
        for (int cs = 0; cs < 8; cs++){
            float2 c = genv[b*SB + cs*32 + lane];
            cx[cs] = c.x; cy[cs] = c.y; csum[cs] = 0.0f;
        }

        bool diag = (a == b);

        #pragma unroll 1
        for (int r = 0; r < 32; r++){
            int rloc = w * 32 + r;
            float2 rp = shr[rloc];
            int rl = diag ? rloc : -1;
            float rs = 0.0f;
            #pragma unroll
            for (int cs = 0; cs < 8; cs++){
                float dx = rp.x - cx[cs];
                float dy = rp.y - cy[cs];
                float d  = fsqrt_fast(fmaf(dy, dy, dx*dx));
                float e  = fexp2_fast(fmaf(d, -KCONST, BIASC));
                if (cs*32 + lane == rl) e = 0.0f;
                rs += e;
                csum[cs] += e;
            }
            #pragma unroll
            for (int o = 16; o; o >>= 1) rs += __shfl_xor_sync(0xffffffffu, rs, o);
            if (lane == 0) g_pneg[b][a*SB + rloc] = rs;
        }

        if (!diag){
            #pragma unroll
            for (int cs = 0; cs < 8; cs++) csum_sh[w][cs*32 + lane] = csum[cs];
            __syncthreads();
            for (int c = tid; c < SB; c += 256){
                float s = 0.0f;
                #pragma unroll
                for (int ww = 0; ww < 8; ww++) s += csum_sh[ww][c];
                g_pneg[a][b*SB + c] = s;
            }
        }
    }
}

// ---------------- Final reduce ----------------
__global__ __launch_bounds__(256) void reduce_kernel(float* __restrict__ out)
{
    int i = blockIdx.x * 256 + threadIdx.x;
    float sp = 0.0f, sn = 0.0f;
    #pragma unroll
    for (int k = 0; k < NB; k++) sp += g_ppos[k][i];
    #pragma unroll
    for (int k = 0; k < NB; k++) sn += g_pneg[k][i];
    out[i] = TLN2C * (flog2_fast(sn) - flog2_fast(sp));
}

extern "C" void kernel_launch(void* const* d_in, const int* in_sizes, int n_in,
                              void* d_out, int out_size)
{
    const float* pos = (const float*)d_in[0];
    const float* z   = (const float*)d_in[1];
    const float* W1  = (const float*)d_in[2];  const float* b1 = (const float*)d_in[3];
    const float* W2  = (const float*)d_in[4];  const float* b2 = (const float*)d_in[5];
    const float* W3  = (const float*)d_in[6];  const float* b3 = (const float*)d_in[7];
    const float* W4  = (const float*)d_in[8];  const float* b4 = (const float*)d_in[9];
    const float* W5  = (const float*)d_in[10]; const float* b5 = (const float*)d_in[11];
    (void)in_sizes; (void)n_in; (void)out_size;

    cudaFuncSetAttribute(mlp_wmma_kernel, cudaFuncAttributeMaxDynamicSharedMemorySize, SM_TOT);

    prep_kernel<<<(W_ELEMS + 255) / 256, 256>>>(W1, W2, W3, W4);
    mlp_wmma_kernel<<<N_PTS / RB, 256, SM_TOT>>>(z, b1, b2, b3, b4, W5, b5);
    energy_kernel<<<POS_BLOCKS + NEG_TILES, 256>>>(pos);
    reduce_kernel<<<N_PTS / 256, 256>>>((float*)d_out);
}